// round 16
// baseline (speedup 1.0000x reference)
#include <cuda_runtime.h>
#include <cuda_fp16.h>
#include <cstdint>
#include <math.h>

// Problem constants
#define B_   8
#define S_   4096
#define E_   1024
#define H_   16
#define D_   64
#define M1   (B_ * S_)        // 32768

// Scratch (device globals)
__device__ __half g_a16[M1 * E_];    // img in fp16
__device__ __half g_vit[M1 * E_];    // v_it in fp16
__device__ float  g_kti[B_ * E_];    // k_ti, pre-scaled by 0.125
__device__ float  g_vti[B_ * E_];
__device__ __half g_cat[M1 * E_];    // img_out in fp16
__device__ __half g_s1h[M1 * 256];   // img-attention logits (pre-scaled, +c), fp16
__device__ __half g_att2[M1 * 256];  // text attention weights (fp16)
__device__ __half g_Qt[B_ * 256 * E_];   // 0.125 * Q^T per batch [b][(q,l)][e]
__device__ float  g_c[B_ * 256];     // 0.125 * score bias correction
__device__ __half g_Pt[B_ * E_ * 256];   // P^T per batch [b][n][(q,l)]
__device__ float  g_wkT[E_ * E_];    // W_kit^T fp32 (feeds compute_Q)
__device__ __half g_wvT[E_ * E_];
__device__ __half g_woT[E_ * E_];

struct alignas(8) half4 { __half2 a, b; };

// ---------------------------------------------------------------------------
// helpers
// ---------------------------------------------------------------------------
__device__ __forceinline__ uint32_t smem_u32(const void* p) {
    uint32_t a;
    asm("{ .reg .u64 t; cvta.to.shared.u64 t, %1; cvt.u32.u64 %0, t; }" : "=r"(a) : "l"(p));
    return a;
}
__device__ __forceinline__ void cp_async16(uint32_t dst, const void* src) {
    asm volatile("cp.async.cg.shared.global [%0], [%1], 16;" :: "r"(dst), "l"(src) : "memory");
}
__device__ __forceinline__ void cp_commit() {
    asm volatile("cp.async.commit_group;" ::: "memory");
}
template <int N> __device__ __forceinline__ void cp_wait() {
    asm volatile("cp.async.wait_group %0;" :: "n"(N) : "memory");
}
__device__ __forceinline__ void mma_f16(float* d, const uint32_t* a, const uint32_t* b) {
    asm volatile(
        "mma.sync.aligned.m16n8k16.row.col.f32.f16.f16.f32 "
        "{%0,%1,%2,%3}, {%4,%5,%6,%7}, {%8,%9}, {%0,%1,%2,%3};"
        : "+f"(d[0]), "+f"(d[1]), "+f"(d[2]), "+f"(d[3])
        : "r"(a[0]), "r"(a[1]), "r"(a[2]), "r"(a[3]), "r"(b[0]), "r"(b[1]));
}

// ---------------------------------------------------------------------------
// Tensor-core fp16 GEMM (fp32 accum), dual-sided, per-batch bias stride,
// linearMap tail-packing.
// ---------------------------------------------------------------------------
#define STG 3
#define ROWH 72
#define TILE_BYTES (128 * ROWH * 2)
#define STAGE_BYTES (2 * TILE_BYTES)
#define GEMM_SMEM (STG * STAGE_BYTES)      // 110592

__global__ __launch_bounds__(128, 2)
void gemm_tc(const __half* __restrict__ A1, int Kd1,
             const __half* __restrict__ Wt1, const float* __restrict__ bias1, int biasB1,
             void* __restrict__ C1, int Nout1, int wtB1, int outOff1, int outHalf1,
             const __half* __restrict__ A2, int Kd2,
             const __half* __restrict__ Wt2, const float* __restrict__ bias2, int biasB2,
             void* __restrict__ C2, int Nout2, int wtB2, int outOff2, int outHalf2,
             int nsplit, int mtPerB, int outBStride, int linearMap)
{
    extern __shared__ char smem[];
    const uint32_t sbase = smem_u32(smem);
    const int tid = threadIdx.x;
    const int wid = tid >> 5, lane = tid & 31;
    const int g = lane >> 2, tg = lane & 3;

    int ntile, mtile, side2;
    if (linearMap) {
        int lin = blockIdx.x + gridDim.x * blockIdx.y;
        const int c1 = nsplit * gridDim.y;
        if (lin < c1) {
            side2 = 0; ntile = lin % nsplit; mtile = lin / nsplit;
        } else {
            lin -= c1;
            const int n2 = gridDim.x - nsplit;
            side2 = 1; ntile = lin % n2; mtile = lin / n2;
        }
    } else {
        ntile = blockIdx.x; mtile = blockIdx.y;
        side2 = (ntile >= nsplit);
        if (side2) ntile -= nsplit;
    }

    const __half* AU; int Kd; const __half* WtU; const float* biasU; int biasBU;
    void* CU; int NoutU, wtBU, outOffU, outHalfU;
    if (!side2) {
        AU = A1; Kd = Kd1; WtU = Wt1; biasU = bias1; biasBU = biasB1; CU = C1;
        NoutU = Nout1; wtBU = wtB1; outOffU = outOff1; outHalfU = outHalf1;
    } else {
        AU = A2; Kd = Kd2; WtU = Wt2; biasU = bias2; biasBU = biasB2; CU = C2;
        NoutU = Nout2; wtBU = wtB2; outOffU = outOff2; outHalfU = outHalf2;
    }

    const int batch = mtile / mtPerB;
    const int mloc  = mtile % mtPerB;
    const int nbase = (wid >> 1) * 64;
    const int mbase = (wid & 1) * 64;

    const __half* Wrow = WtU + (size_t)batch * wtBU + (size_t)ntile * 128 * Kd;
    const __half* Arow = AU + (size_t)mtile * 128 * Kd;

    int srcOff[8];
    uint32_t dstOff[8];
    #pragma unroll
    for (int i = 0; i < 8; i++) {
        int c = tid + i * 128;
        int r = c >> 3, c8 = c & 7;
        srcOff[i] = r * Kd + c8 * 8;
        dstOff[i] = (uint32_t)(r * (ROWH * 2) + c8 * 16);
    }

    auto load_stage = [&](int it) {
        const uint32_t wbuf = sbase + (it % STG) * STAGE_BYTES;
        const uint32_t abuf = wbuf + TILE_BYTES;
        const __half* wk = Wrow + it * 64;
        const __half* ak = Arow + it * 64;
        #pragma unroll
        for (int i = 0; i < 8; i++) cp_async16(wbuf + dstOff[i], wk + srcOff[i]);
        #pragma unroll
        for (int i = 0; i < 8; i++) cp_async16(abuf + dstOff[i], ak + srcOff[i]);
    };

    float acc[4][8][4];
    #pragma unroll
    for (int i = 0; i < 4; i++)
        #pragma unroll
        for (int j = 0; j < 8; j++)
            #pragma unroll
            for (int e = 0; e < 4; e++) acc[i][j][e] = 0.f;

    #pragma unroll
    for (int p = 0; p < STG - 1; p++) { load_stage(p); cp_commit(); }

    const int NIT = Kd / 64;
    for (int it = 0; it < NIT; ++it) {
        cp_wait<STG - 2>();
        __syncthreads();
        if (it + STG - 1 < NIT) load_stage(it + STG - 1);
        cp_commit();

        const uint32_t* wt = (const uint32_t*)(smem + (it % STG) * STAGE_BYTES);
        const uint32_t* at = (const uint32_t*)(smem + (it % STG) * STAGE_BYTES + TILE_BYTES);

        #pragma unroll
        for (int ks = 0; ks < 4; ks++) {
            const int col = ks * 8 + tg;
            uint32_t afr[4][4];
            #pragma unroll
            for (int i = 0; i < 4; i++) {
                const int r0 = nbase + i * 16 + g;
                afr[i][0] = wt[r0 * 36 + col];
                afr[i][1] = wt[(r0 + 8) * 36 + col];
                afr[i][2] = wt[r0 * 36 + col + 4];
                afr[i][3] = wt[(r0 + 8) * 36 + col + 4];
            }
            uint32_t bfr[8][2];
            #pragma unroll
            for (int j = 0; j < 8; j++) {
                const int r = mbase + j * 8 + g;
                bfr[j][0] = at[r * 36 + col];
                bfr[j][1] = at[r * 36 + col + 4];
            }
            #pragma unroll
            for (int i = 0; i < 4; i++)
                #pragma unroll
                for (int j = 0; j < 8; j++)
                    mma_f16(acc[i][j], afr[i], bfr[j]);
        }
    }

    __syncthreads();
    float* cs = (float*)smem;        // [128 n][129 m]
    #pragma unroll
    for (int i = 0; i < 4; i++) {
        #pragma unroll
        for (int j = 0; j < 8; j++) {
            const int n = nbase + i * 16 + g;
            const int m = mbase + j * 8 + tg * 2;
            cs[n * 129 + m]           = acc[i][j][0];
            cs[n * 129 + m + 1]       = acc[i][j][1];
            cs[(n + 8) * 129 + m]     = acc[i][j][2];
            cs[(n + 8) * 129 + m + 1] = acc[i][j][3];
        }
    }
    __syncthreads();

    const int m = tid;
    const size_t outRow = (size_t)batch * outBStride + outOffU + mloc * 128 + m;
    const float* brow = biasU + (size_t)batch * biasBU + ntile * 128;
    if (!outHalfU) {
        float* Crow = (float*)CU + outRow * NoutU + ntile * 128;
        #pragma unroll
        for (int q = 0; q < 32; q++) {
            float4 v;
            v.x = cs[(q * 4 + 0) * 129 + m] + brow[q * 4 + 0];
            v.y = cs[(q * 4 + 1) * 129 + m] + brow[q * 4 + 1];
            v.z = cs[(q * 4 + 2) * 129 + m] + brow[q * 4 + 2];
            v.w = cs[(q * 4 + 3) * 129 + m] + brow[q * 4 + 3];
            *(float4*)(Crow + q * 4) = v;
        }
    } else {
        __half* Crow = (__half*)CU + outRow * NoutU + ntile * 128;
        #pragma unroll
        for (int q = 0; q < 16; q++) {
            uint4 u;
            __half2 h;
            h = __floats2half2_rn(cs[(q*8+0)*129+m] + brow[q*8+0], cs[(q*8+1)*129+m] + brow[q*8+1]);
            u.x = *reinterpret_cast<uint32_t*>(&h);
            h = __floats2half2_rn(cs[(q*8+2)*129+m] + brow[q*8+2], cs[(q*8+3)*129+m] + brow[q*8+3]);
            u.y = *reinterpret_cast<uint32_t*>(&h);
            h = __floats2half2_rn(cs[(q*8+4)*129+m] + brow[q*8+4], cs[(q*8+5)*129+m] + brow[q*8+5]);
            u.z = *reinterpret_cast<uint32_t*>(&h);
            h = __floats2half2_rn(cs[(q*8+6)*129+m] + brow[q*8+6], cs[(q*8+7)*129+m] + brow[q*8+7]);
            u.w = *reinterpret_cast<uint32_t*>(&h);
            *(uint4*)(Crow + q * 8) = u;
        }
    }
}

// ---------------------------------------------------------------------------
__global__ __launch_bounds__(256)
void cvt_img(const float* __restrict__ in, __half* __restrict__ out)
{
    const int i = blockIdx.x * 256 + threadIdx.x;
    float4 v = ((const float4*)in)[i];
    __half2 h01 = __floats2half2_rn(v.x, v.y);
    __half2 h23 = __floats2half2_rn(v.z, v.w);
    ((__half2*)out)[i * 2]     = h01;
    ((__half2*)out)[i * 2 + 1] = h23;
}

__global__ __launch_bounds__(256)
void transpose_all(const float* __restrict__ Wk, const float* __restrict__ Wv,
                   const float* __restrict__ Wo)
{
    __shared__ float t[32][33];
    const int z = blockIdx.z;
    const float* W = (z == 0) ? Wk : (z == 1) ? Wv : Wo;

    const int x = blockIdx.x * 32 + threadIdx.x;
    const int y0 = blockIdx.y * 32 + threadIdx.y;
    #pragma unroll
    for (int i = 0; i < 32; i += 8)
        t[threadIdx.y + i][threadIdx.x] = W[(size_t)(y0 + i) * E_ + x];
    __syncthreads();
    const int x2 = blockIdx.y * 32 + threadIdx.x;
    const int y2 = blockIdx.x * 32 + threadIdx.y;
    if (z == 0) {
        #pragma unroll
        for (int i = 0; i < 32; i += 8)
            g_wkT[(size_t)(y2 + i) * E_ + x2] = t[threadIdx.x][threadIdx.y + i];
    } else {
        __half* WT = (z == 1) ? g_wvT : g_woT;
        #pragma unroll
        for (int i = 0; i < 32; i += 8)
            WT[(size_t)(y2 + i) * E_ + x2] = __float2half_rn(t[threadIdx.x][threadIdx.y + i]);
    }
}

// kti pre-scaled by 0.125 (it feeds only the s2 dot-product)
__global__ __launch_bounds__(256)
void small_proj(const float* __restrict__ text,
                const float* __restrict__ Wk, const float* __restrict__ bk,
                const float* __restrict__ Wv, const float* __restrict__ bv)
{
    const int b = blockIdx.y;
    const int n = blockIdx.x * 256 + threadIdx.x;
    __shared__ float ts[E_];
    for (int i = threadIdx.x; i < E_; i += 256) ts[i] = text[b * E_ + i];
    __syncthreads();
    float accK = 0.f, accV = 0.f;
    for (int k = 0; k < E_; k++) {
        const float t = ts[k];
        accK += t * Wk[(size_t)k * E_ + n];
        accV += t * Wv[(size_t)k * E_ + n];
    }
    g_kti[b * E_ + n] = (accK + bk[n]) * 0.125f;
    g_vti[b * E_ + n] = accV + bv[n];
}

// Qt pre-scaled by 0.125
__global__ __launch_bounds__(256)
void compute_Q(const float* __restrict__ text)
{
    const int e = blockIdx.x * 256 + threadIdx.x;
    const int ql = blockIdx.y;
    const int q = ql >> 4, l = ql & 15;

    __shared__ float tx[B_][D_];
    for (int i = threadIdx.x; i < B_ * D_; i += 256)
        tx[i / D_][i % D_] = text[(i / D_) * E_ + q * 64 + (i % D_)];
    __syncthreads();

    float acc[B_];
    #pragma unroll
    for (int b = 0; b < B_; b++) acc[b] = 0.f;
    #pragma unroll 8
    for (int d = 0; d < D_; d++) {
        const float w = g_wkT[(size_t)(l * 64 + d) * E_ + e];
        #pragma unroll
        for (int b = 0; b < B_; b++) acc[b] += w * tx[b][d];
    }
    #pragma unroll
    for (int b = 0; b < B_; b++)
        g_Qt[(size_t)b * (256 * E_) + (size_t)ql * E_ + e] = __float2half_rn(acc[b] * 0.125f);
}

// c pre-scaled by 0.125
__global__ __launch_bounds__(256)
void compute_c(const float* __restrict__ text, const float* __restrict__ bk)
{
    const int b = blockIdx.x;
    const int ql = threadIdx.x;
    const int q = ql >> 4, l = ql & 15;
    float acc = 0.f;
    #pragma unroll 8
    for (int d = 0; d < D_; d++)
        acc += text[b * E_ + q * 64 + d] * bk[l * 64 + d];
    g_c[b * 256 + ql] = acc * 0.125f;
}

__global__ __launch_bounds__(256)
void compute_Pt(const float* __restrict__ W_out)
{
    const int n = blockIdx.x * 256 + threadIdx.x;
    const int ql = blockIdx.y;
    const int q = ql >> 4, l = ql & 15;

    __shared__ float vt[B_][D_];
    for (int i = threadIdx.x; i < B_ * D_; i += 256)
        vt[i / D_][i % D_] = g_vti[(i / D_) * E_ + l * 64 + (i % D_)];
    __syncthreads();

    float acc[B_];
    #pragma unroll
    for (int b = 0; b < B_; b++) acc[b] = 0.f;
    #pragma unroll 8
    for (int d = 0; d < D_; d++) {
        const float w = W_out[(size_t)(q * 64 + d) * E_ + n];
        #pragma unroll
        for (int b = 0; b < B_; b++) acc[b] += w * vt[b][d];
    }
    #pragma unroll
    for (int b = 0; b < B_; b++)
        g_Pt[(size_t)b * (E_ * 256) + (size_t)n * 256 + ql] = __float2half_rn(acc[b]);
}

// ---------------------------------------------------------------------------
// Fused per-position attention, 4 positions/block, fp16 smem tiles,
// fp16 pre-scaled logits (c already folded in by the GEMM bias).
// ---------------------------------------------------------------------------
#define NPOS 4

__global__ __launch_bounds__(256)
void attention_pos()
{
    const int n0 = blockIdx.x * NPOS;
    const int b = blockIdx.y;
    const int tid = threadIdx.x;

    __shared__ half4 xs_h[NPOS][256];        // img rows, fp16
    __shared__ half4 vs_h[NPOS][256];        // v_it rows, fp16
    __shared__ float2 kt2[H_][33];           // 0.125*k_ti, float2-padded
    __shared__ float att1[NPOS][H_][H_];

    const size_t r0 = (size_t)b * S_ + n0;
    {
        const int e = tid * 4, lL = e >> 6, j = e & 63;
        #pragma unroll
        for (int p = 0; p < NPOS; p++) {
            xs_h[p][tid] = ((const half4*)g_a16)[(r0 + p) * 256 + tid];
            vs_h[p][tid] = ((const half4*)g_vit)[(r0 + p) * 256 + tid];
        }
        float4 vkt = ((const float4*)g_kti)[b * 256 + tid];
        kt2[lL][(j >> 1) + 0] = make_float2(vkt.x, vkt.y);
        kt2[lL][(j >> 1) + 1] = make_float2(vkt.z, vkt.w);
    }
    float s1[NPOS];
    #pragma unroll
    for (int p = 0; p < NPOS; p++)
        s1[p] = __half2float(g_s1h[(r0 + p) * 256 + tid]);
    __syncthreads();

    const int q = tid >> 4;
    const int l = tid & 15;

    // s2: img row (half2 in smem) dot pre-scaled k_ti head
    const __half2* xp[NPOS];
    #pragma unroll
    for (int p = 0; p < NPOS; p++)
        xp[p] = (const __half2*)xs_h[p] + q * 32;

    float s2[NPOS];
    #pragma unroll
    for (int p = 0; p < NPOS; p++) s2[p] = 0.f;
    #pragma unroll
    for (int j2 = 0; j2 < 32; j2++) {
        const float2 kt = kt2[l][j2];
        #pragma unroll
        for (int p = 0; p < NPOS; p++) {
            const float2 xv = __half22float2(xp[p][j2]);
            s2[p] += xv.x * kt.x + xv.y * kt.y;
        }
    }

    float m1[NPOS], m2[NPOS];
    #pragma unroll
    for (int p = 0; p < NPOS; p++) { m1[p] = s1[p]; m2[p] = s2[p]; }
    #pragma unroll
    for (int o = 8; o > 0; o >>= 1) {
        #pragma unroll
        for (int p = 0; p < NPOS; p++) {
            m1[p] = fmaxf(m1[p], __shfl_xor_sync(0xffffffffu, m1[p], o));
            m2[p] = fmaxf(m2[p], __shfl_xor_sync(0xffffffffu, m2[p], o));
        }
    }
    float e1[NPOS], e2[NPOS], z1[NPOS], z2[NPOS];
    #pragma unroll
    for (int p = 0; p < NPOS; p++) {
        e1[p] = expf(s1[p] - m1[p]); e2[p] = expf(s2[p] - m2[p]);
        z1[p] = e1[p]; z2[p] = e2[p];
    }
    #pragma unroll
    for (int o = 8; o > 0; o >>= 1) {
        #pragma unroll
        for (int p = 0; p < NPOS; p++) {
            z1[p] += __shfl_xor_sync(0xffffffffu, z1[p], o);
            z2[p] += __shfl_xor_sync(0xffffffffu, z2[p], o);
        }
    }
    #pragma unroll
    for (int p = 0; p < NPOS; p++) {
        att1[p][q][l] = e1[p] / z1[p];
        g_att2[(r0 + p) * 256 + tid] = __float2half_rn(e2[p] / z2[p]);
    }
    __syncthreads();

    const int qq = tid >> 4;
    const int dv = tid & 15;
    half4* cat4 = (half4*)g_cat;
    #pragma unroll
    for (int p = 0; p < NPOS; p++) {
        float4 o1 = make_float4(0.f, 0.f, 0.f, 0.f);
        #pragma unroll
        for (int ll = 0; ll < H_; ll++) {
            const float a1 = att1[p][qq][ll];
            const half4 hv = vs_h[p][ll * 16 + dv];
            const float2 v0 = __half22float2(hv.a);
            const float2 v1 = __half22float2(hv.b);
            o1.x += a1 * v0.x; o1.y += a1 * v0.y; o1.z += a1 * v1.x; o1.w += a1 * v1.y;
        }
        half4 h;
        h.a = __floats2half2_rn(o1.x, o1.y);
        h.b = __floats2half2_rn(o1.z, o1.w);
        cat4[(r0 + p) * 256 + tid] = h;
    }
}

// ---------------------------------------------------------------------------
extern "C" void kernel_launch(void* const* d_in, const int* in_sizes, int n_in,
                              void* d_out, int out_size)
{
    const float* img   = (const float*)d_in[0];
    const float* text  = (const float*)d_in[1];
    const float* W_kit = (const float*)d_in[2];
    const float* b_kit = (const float*)d_in[3];
    const float* W_vit = (const float*)d_in[4];
    const float* b_vit = (const float*)d_in[5];
    const float* W_kti = (const float*)d_in[6];
    const float* b_kti = (const float*)d_in[7];
    const float* W_vti = (const float*)d_in[8];
    const float* b_vti = (const float*)d_in[9];
    const float* W_out = (const float*)d_in[10];
    const float* b_out = (const float*)d_in[11];
    float* out = (float*)d_out;

    __half *a16, *vit, *cat, *s1h, *att2, *Qt, *Pt, *wvT, *woT;
    float *cvec;
    cudaGetSymbolAddress((void**)&a16, g_a16);
    cudaGetSymbolAddress((void**)&vit, g_vit);
    cudaGetSymbolAddress((void**)&cat, g_cat);
    cudaGetSymbolAddress((void**)&s1h, g_s1h);
    cudaGetSymbolAddress((void**)&att2, g_att2);
    cudaGetSymbolAddress((void**)&Qt, g_Qt);
    cudaGetSymbolAddress((void**)&Pt, g_Pt);
    cudaGetSymbolAddress((void**)&wvT, g_wvT);
    cudaGetSymbolAddress((void**)&woT, g_woT);
    cudaGetSymbolAddress((void**)&cvec, g_c);

    static cudaStream_t sA = nullptr, sB = nullptr;
    static cudaEvent_t evRoot = nullptr, evA = nullptr, evB = nullptr;
    if (!sA) {
        cudaStreamCreateWithFlags(&sA, cudaStreamNonBlocking);
        cudaStreamCreateWithFlags(&sB, cudaStreamNonBlocking);
        cudaEventCreateWithFlags(&evRoot, cudaEventDisableTiming);
        cudaEventCreateWithFlags(&evA, cudaEventDisableTiming);
        cudaEventCreateWithFlags(&evB, cudaEventDisableTiming);
        cudaFuncSetAttribute(gemm_tc, cudaFuncAttributeMaxDynamicSharedMemorySize, GEMM_SMEM);
    }

    // fork side streams off the capture-origin stream
    cudaEventRecord(evRoot, 0);
    cudaStreamWaitEvent(sA, evRoot, 0);
    cudaStreamWaitEvent(sB, evRoot, 0);

    // stream A: text-side prep (off critical path until attention)
    small_proj<<<dim3(E_ / 256, B_), 256, 0, sA>>>(text, W_kti, b_kti, W_vti, b_vti);
    compute_Pt<<<dim3(4, 256), 256, 0, sA>>>(W_out);
    cudaEventRecord(evA, sA);

    // stream B: img conversion (parallel with main prep)
    cvt_img<<<(M1 * E_ / 4) / 256, 256, 0, sB>>>(img, a16);
    cudaEventRecord(evB, sB);

    // main: weight transposes -> Qt, c (c feeds GEMM1's bias)
    transpose_all<<<dim3(32, 32, 3), dim3(32, 8)>>>(W_kit, W_vit, W_out);
    compute_Q<<<dim3(4, 256), 256>>>(text);
    compute_c<<<B_, 256>>>(text, b_kit);

    // GEMM1 (whole): v_it projection + img-attn logits (c folded via per-batch bias)
    cudaStreamWaitEvent(0, evB, 0);
    gemm_tc<<<dim3(10, 256), 128, GEMM_SMEM>>>(
        a16, 1024, wvT, b_vit, 0, vit, 1024, 0, 0, 1,
        a16, 1024, Qt, cvec, 256, s1h, 256, 256 * E_, 0, 1,
        8, 32, 4096, 0);

    // fused attention -> img_out (fp16) + att2 weights (fp16)
    cudaStreamWaitEvent(0, evA, 0);
    attention_pos<<<dim3(S_ / NPOS, B_), 256>>>();

    // single fused final projection (linearMap=1: cheap K=256 tiles in tail)
    gemm_tc<<<dim3(16, 256), 128, GEMM_SMEM>>>(
        cat, 1024, woT, b_out, 0, out, 1024, 0, 0, 0,
        att2, 256, Pt, b_out, 0, out, 1024, 256 * E_, 4096, 0,
        8, 32, 8192, 1);
}

// round 17
// speedup vs baseline: 1.0425x; 1.0425x over previous
#include <cuda_runtime.h>
#include <cuda_fp16.h>
#include <cstdint>
#include <math.h>

// Problem constants
#define B_   8
#define S_   4096
#define E_   1024
#define H_   16
#define D_   64
#define M1   (B_ * S_)        // 32768

// Scratch (device globals)
__device__ __half g_a16[M1 * E_];    // img in fp16
__device__ __half g_vit[M1 * E_];    // v_it in fp16
__device__ float  g_kti[B_ * E_];    // k_ti, pre-scaled by 0.125
__device__ float  g_vti[B_ * E_];
__device__ __half g_cat[M1 * E_];    // img_out in fp16
__device__ __half g_s1h[M1 * 256];   // img-attention logits (pre-scaled, +c), fp16
__device__ __half g_att2[M1 * 256];  // text attention weights (fp16)
__device__ __half g_Qt[B_ * 256 * E_];   // 0.125 * Q^T per batch [b][(q,l)][e]
__device__ float  g_c[B_ * 256];     // 0.125 * score bias correction
__device__ __half g_Pt[B_ * E_ * 256];   // P^T per batch [b][n][(q,l)]
__device__ float  g_wkT[E_ * E_];    // W_kit^T fp32 (feeds compute_Q)
__device__ __half g_wvT[E_ * E_];
__device__ __half g_woT[E_ * E_];

struct alignas(8) half4 { __half2 a, b; };

// ---------------------------------------------------------------------------
// helpers
// ---------------------------------------------------------------------------
__device__ __forceinline__ uint32_t smem_u32(const void* p) {
    uint32_t a;
    asm("{ .reg .u64 t; cvta.to.shared.u64 t, %1; cvt.u32.u64 %0, t; }" : "=r"(a) : "l"(p));
    return a;
}
__device__ __forceinline__ void cp_async16(uint32_t dst, const void* src) {
    asm volatile("cp.async.cg.shared.global [%0], [%1], 16;" :: "r"(dst), "l"(src) : "memory");
}
__device__ __forceinline__ void cp_commit() {
    asm volatile("cp.async.commit_group;" ::: "memory");
}
template <int N> __device__ __forceinline__ void cp_wait() {
    asm volatile("cp.async.wait_group %0;" :: "n"(N) : "memory");
}
__device__ __forceinline__ void mma_f16(float* d, const uint32_t* a, const uint32_t* b) {
    asm volatile(
        "mma.sync.aligned.m16n8k16.row.col.f32.f16.f16.f32 "
        "{%0,%1,%2,%3}, {%4,%5,%6,%7}, {%8,%9}, {%0,%1,%2,%3};"
        : "+f"(d[0]), "+f"(d[1]), "+f"(d[2]), "+f"(d[3])
        : "r"(a[0]), "r"(a[1]), "r"(a[2]), "r"(a[3]), "r"(b[0]), "r"(b[1]));
}
__device__ __forceinline__ void ldsm_x4(uint32_t* r, uint32_t addr) {
    asm volatile("ldmatrix.sync.aligned.m8n8.x4.shared.b16 {%0,%1,%2,%3}, [%4];"
        : "=r"(r[0]), "=r"(r[1]), "=r"(r[2]), "=r"(r[3]) : "r"(addr));
}

// ---------------------------------------------------------------------------
// Tensor-core fp16 GEMM (fp32 accum), dual-sided, per-batch bias stride,
// linearMap tail-packing, ldmatrix fragment loads.
// ---------------------------------------------------------------------------
#define STG 3
#define ROWH 72
#define ROWB 144                           // bytes per smem row
#define TILE_BYTES (128 * ROWB)
#define STAGE_BYTES (2 * TILE_BYTES)
#define GEMM_SMEM (STG * STAGE_BYTES)      // 110592

__global__ __launch_bounds__(128, 2)
void gemm_tc(const __half* __restrict__ A1, int Kd1,
             const __half* __restrict__ Wt1, const float* __restrict__ bias1, int biasB1,
             void* __restrict__ C1, int Nout1, int wtB1, int outOff1, int outHalf1,
             const __half* __restrict__ A2, int Kd2,
             const __half* __restrict__ Wt2, const float* __restrict__ bias2, int biasB2,
             void* __restrict__ C2, int Nout2, int wtB2, int outOff2, int outHalf2,
             int nsplit, int mtPerB, int outBStride, int linearMap)
{
    extern __shared__ char smem[];
    const uint32_t sbase = smem_u32(smem);
    const int tid = threadIdx.x;
    const int wid = tid >> 5, lane = tid & 31;
    const int g = lane >> 2, tg = lane & 3;

    int ntile, mtile, side2;
    if (linearMap) {
        int lin = blockIdx.x + gridDim.x * blockIdx.y;
        const int c1 = nsplit * gridDim.y;
        if (lin < c1) {
            side2 = 0; ntile = lin % nsplit; mtile = lin / nsplit;
        } else {
            lin -= c1;
            const int n2 = gridDim.x - nsplit;
            side2 = 1; ntile = lin % n2; mtile = lin / n2;
        }
    } else {
        ntile = blockIdx.x; mtile = blockIdx.y;
        side2 = (ntile >= nsplit);
        if (side2) ntile -= nsplit;
    }

    const __half* AU; int Kd; const __half* WtU; const float* biasU; int biasBU;
    void* CU; int NoutU, wtBU, outOffU, outHalfU;
    if (!side2) {
        AU = A1; Kd = Kd1; WtU = Wt1; biasU = bias1; biasBU = biasB1; CU = C1;
        NoutU = Nout1; wtBU = wtB1; outOffU = outOff1; outHalfU = outHalf1;
    } else {
        AU = A2; Kd = Kd2; WtU = Wt2; biasU = bias2; biasBU = biasB2; CU = C2;
        NoutU = Nout2; wtBU = wtB2; outOffU = outOff2; outHalfU = outHalf2;
    }

    const int batch = mtile / mtPerB;
    const int mloc  = mtile % mtPerB;
    const int nbase = (wid >> 1) * 64;
    const int mbase = (wid & 1) * 64;

    const __half* Wrow = WtU + (size_t)batch * wtBU + (size_t)ntile * 128 * Kd;
    const __half* Arow = AU + (size_t)mtile * 128 * Kd;

    int srcOff[8];
    uint32_t dstOff[8];
    #pragma unroll
    for (int i = 0; i < 8; i++) {
        int c = tid + i * 128;
        int r = c >> 3, c8 = c & 7;
        srcOff[i] = r * Kd + c8 * 8;
        dstOff[i] = (uint32_t)(r * ROWB + c8 * 16);
    }

    auto load_stage = [&](int it) {
        const uint32_t wbuf = sbase + (it % STG) * STAGE_BYTES;
        const uint32_t abuf = wbuf + TILE_BYTES;
        const __half* wk = Wrow + it * 64;
        const __half* ak = Arow + it * 64;
        #pragma unroll
        for (int i = 0; i < 8; i++) cp_async16(wbuf + dstOff[i], wk + srcOff[i]);
        #pragma unroll
        for (int i = 0; i < 8; i++) cp_async16(abuf + dstOff[i], ak + srcOff[i]);
    };

    // ldmatrix per-lane offsets
    const uint32_t aOff = (uint32_t)((lane & 15) * ROWB + (lane >> 4) * 16);
    const uint32_t bOff = (uint32_t)((((lane >> 4) * 8) + (lane & 7)) * ROWB
                                     + (((lane >> 3) & 1) * 16));

    float acc[4][8][4];
    #pragma unroll
    for (int i = 0; i < 4; i++)
        #pragma unroll
        for (int j = 0; j < 8; j++)
            #pragma unroll
            for (int e = 0; e < 4; e++) acc[i][j][e] = 0.f;

    #pragma unroll
    for (int p = 0; p < STG - 1; p++) { load_stage(p); cp_commit(); }

    const int NIT = Kd / 64;
    for (int it = 0; it < NIT; ++it) {
        cp_wait<STG - 2>();
        __syncthreads();
        if (it + STG - 1 < NIT) load_stage(it + STG - 1);
        cp_commit();

        const uint32_t wtb = sbase + (it % STG) * STAGE_BYTES;
        const uint32_t atb = wtb + TILE_BYTES;

        #pragma unroll
        for (int ks = 0; ks < 4; ks++) {
            const uint32_t kByte = (uint32_t)(ks * 32);
            uint32_t afr[4][4];
            #pragma unroll
            for (int i = 0; i < 4; i++)
                ldsm_x4(afr[i], wtb + (uint32_t)((nbase + i * 16) * ROWB) + aOff + kByte);
            uint32_t bfr[8][2];
            #pragma unroll
            for (int jj = 0; jj < 4; jj++) {
                uint32_t r[4];
                ldsm_x4(r, atb + (uint32_t)((mbase + jj * 16) * ROWB) + bOff + kByte);
                bfr[jj * 2][0] = r[0]; bfr[jj * 2][1] = r[1];
                bfr[jj * 2 + 1][0] = r[2]; bfr[jj * 2 + 1][1] = r[3];
            }
            #pragma unroll
            for (int i = 0; i < 4; i++)
                #pragma unroll
                for (int j = 0; j < 8; j++)
                    mma_f16(acc[i][j], afr[i], bfr[j]);
        }
    }

    __syncthreads();
    float* cs = (float*)smem;        // [128 n][129 m]
    #pragma unroll
    for (int i = 0; i < 4; i++) {
        #pragma unroll
        for (int j = 0; j < 8; j++) {
            const int n = nbase + i * 16 + g;
            const int m = mbase + j * 8 + tg * 2;
            cs[n * 129 + m]           = acc[i][j][0];
            cs[n * 129 + m + 1]       = acc[i][j][1];
            cs[(n + 8) * 129 + m]     = acc[i][j][2];
            cs[(n + 8) * 129 + m + 1] = acc[i][j][3];
        }
    }
    __syncthreads();

    const int m = tid;
    const size_t outRow = (size_t)batch * outBStride + outOffU + mloc * 128 + m;
    const float* brow = biasU + (size_t)batch * biasBU + ntile * 128;
    if (!outHalfU) {
        float* Crow = (float*)CU + outRow * NoutU + ntile * 128;
        #pragma unroll
        for (int q = 0; q < 32; q++) {
            float4 v;
            v.x = cs[(q * 4 + 0) * 129 + m] + brow[q * 4 + 0];
            v.y = cs[(q * 4 + 1) * 129 + m] + brow[q * 4 + 1];
            v.z = cs[(q * 4 + 2) * 129 + m] + brow[q * 4 + 2];
            v.w = cs[(q * 4 + 3) * 129 + m] + brow[q * 4 + 3];
            *(float4*)(Crow + q * 4) = v;
        }
    } else {
        __half* Crow = (__half*)CU + outRow * NoutU + ntile * 128;
        #pragma unroll
        for (int q = 0; q < 16; q++) {
            uint4 u;
            __half2 h;
            h = __floats2half2_rn(cs[(q*8+0)*129+m] + brow[q*8+0], cs[(q*8+1)*129+m] + brow[q*8+1]);
            u.x = *reinterpret_cast<uint32_t*>(&h);
            h = __floats2half2_rn(cs[(q*8+2)*129+m] + brow[q*8+2], cs[(q*8+3)*129+m] + brow[q*8+3]);
            u.y = *reinterpret_cast<uint32_t*>(&h);
            h = __floats2half2_rn(cs[(q*8+4)*129+m] + brow[q*8+4], cs[(q*8+5)*129+m] + brow[q*8+5]);
            u.z = *reinterpret_cast<uint32_t*>(&h);
            h = __floats2half2_rn(cs[(q*8+6)*129+m] + brow[q*8+6], cs[(q*8+7)*129+m] + brow[q*8+7]);
            u.w = *reinterpret_cast<uint32_t*>(&h);
            *(uint4*)(Crow + q * 8) = u;
        }
    }
}

// ---------------------------------------------------------------------------
__global__ __launch_bounds__(256)
void cvt_img(const float* __restrict__ in, __half* __restrict__ out)
{
    const int i = blockIdx.x * 256 + threadIdx.x;
    float4 v = ((const float4*)in)[i];
    __half2 h01 = __floats2half2_rn(v.x, v.y);
    __half2 h23 = __floats2half2_rn(v.z, v.w);
    ((__half2*)out)[i * 2]     = h01;
    ((__half2*)out)[i * 2 + 1] = h23;
}

__global__ __launch_bounds__(256)
void transpose_all(const float* __restrict__ Wk, const float* __restrict__ Wv,
                   const float* __restrict__ Wo)
{
    __shared__ float t[32][33];
    const int z = blockIdx.z;
    const float* W = (z == 0) ? Wk : (z == 1) ? Wv : Wo;

    const int x = blockIdx.x * 32 + threadIdx.x;
    const int y0 = blockIdx.y * 32 + threadIdx.y;
    #pragma unroll
    for (int i = 0; i < 32; i += 8)
        t[threadIdx.y + i][threadIdx.x] = W[(size_t)(y0 + i) * E_ + x];
    __syncthreads();
    const int x2 = blockIdx.y * 32 + threadIdx.x;
    const int y2 = blockIdx.x * 32 + threadIdx.y;
    if (z == 0) {
        #pragma unroll
        for (int i = 0; i < 32; i += 8)
            g_wkT[(size_t)(y2 + i) * E_ + x2] = t[threadIdx.x][threadIdx.y + i];
    } else {
        __half* WT = (z == 1) ? g_wvT : g_woT;
        #pragma unroll
        for (int i = 0; i < 32; i += 8)
            WT[(size_t)(y2 + i) * E_ + x2] = __float2half_rn(t[threadIdx.x][threadIdx.y + i]);
    }
}

// kti pre-scaled by 0.125
__global__ __launch_bounds__(256)
void small_proj(const float* __restrict__ text,
                const float* __restrict__ Wk, const float* __restrict__ bk,
                const float* __restrict__ Wv, const float* __restrict__ bv)
{
    const int b = blockIdx.y;
    const int n = blockIdx.x * 256 + threadIdx.x;
    __shared__ float ts[E_];
    for (int i = threadIdx.x; i < E_; i += 256) ts[i] = text[b * E_ + i];
    __syncthreads();
    float accK = 0.f, accV = 0.f;
    for (int k = 0; k < E_; k++) {
        const float t = ts[k];
        accK += t * Wk[(size_t)k * E_ + n];
        accV += t * Wv[(size_t)k * E_ + n];
    }
    g_kti[b * E_ + n] = (accK + bk[n]) * 0.125f;
    g_vti[b * E_ + n] = accV + bv[n];
}

// Qt pre-scaled by 0.125
__global__ __launch_bounds__(256)
void compute_Q(const float* __restrict__ text)
{
    const int e = blockIdx.x * 256 + threadIdx.x;
    const int ql = blockIdx.y;
    const int q = ql >> 4, l = ql & 15;

    __shared__ float tx[B_][D_];
    for (int i = threadIdx.x; i < B_ * D_; i += 256)
        tx[i / D_][i % D_] = text[(i / D_) * E_ + q * 64 + (i % D_)];
    __syncthreads();

    float acc[B_];
    #pragma unroll
    for (int b = 0; b < B_; b++) acc[b] = 0.f;
    #pragma unroll 8
    for (int d = 0; d < D_; d++) {
        const float w = g_wkT[(size_t)(l * 64 + d) * E_ + e];
        #pragma unroll
        for (int b = 0; b < B_; b++) acc[b] += w * tx[b][d];
    }
    #pragma unroll
    for (int b = 0; b < B_; b++)
        g_Qt[(size_t)b * (256 * E_) + (size_t)ql * E_ + e] = __float2half_rn(acc[b] * 0.125f);
}

// c pre-scaled by 0.125
__global__ __launch_bounds__(256)
void compute_c(const float* __restrict__ text, const float* __restrict__ bk)
{
    const int b = blockIdx.x;
    const int ql = threadIdx.x;
    const int q = ql >> 4, l = ql & 15;
    float acc = 0.f;
    #pragma unroll 8
    for (int d = 0; d < D_; d++)
        acc += text[b * E_ + q * 64 + d] * bk[l * 64 + d];
    g_c[b * 256 + ql] = acc * 0.125f;
}

__global__ __launch_bounds__(256)
void compute_Pt(const float* __restrict__ W_out)
{
    const int n = blockIdx.x * 256 + threadIdx.x;
    const int ql = blockIdx.y;
    const int q = ql >> 4, l = ql & 15;

    __shared__ float vt[B_][D_];
    for (int i = threadIdx.x; i < B_ * D_; i += 256)
        vt[i / D_][i % D_] = g_vti[(i / D_) * E_ + l * 64 + (i % D_)];
    __syncthreads();

    float acc[B_];
    #pragma unroll
    for (int b = 0; b < B_; b++) acc[b] = 0.f;
    #pragma unroll 8
    for (int d = 0; d < D_; d++) {
        const float w = W_out[(size_t)(q * 64 + d) * E_ + n];
        #pragma unroll
        for (int b = 0; b < B_; b++) acc[b] += w * vt[b][d];
    }
    #pragma unroll
    for (int b = 0; b < B_; b++)
        g_Pt[(size_t)b * (E_ * 256) + (size_t)n * 256 + ql] = __float2half_rn(acc[b]);
}

// ---------------------------------------------------------------------------
// Fused per-position attention, 4 positions/block, fp16 smem tiles,
// fp16 pre-scaled logits (c folded via GEMM bias).
// ---------------------------------------------------------------------------
#define NPOS 4

__global__ __launch_bounds__(256)
void attention_pos()
{
    const int n0 = blockIdx.x * NPOS;
    const int b = blockIdx.y;
    const int tid = threadIdx.x;

    __shared__ half4 xs_h[NPOS][256];
    __shared__ half4 vs_h[NPOS][256];
    __shared__ float2 kt2[H_][33];
    __shared__ float att1[NPOS][H_][H_];

    const size_t r0 = (size_t)b * S_ + n0;
    {
        const int e = tid * 4, lL = e >> 6, j = e & 63;
        #pragma unroll
        for (int p = 0; p < NPOS; p++) {
            xs_h[p][tid] = ((const half4*)g_a16)[(r0 + p) * 256 + tid];
            vs_h[p][tid] = ((const half4*)g_vit)[(r0 + p) * 256 + tid];
        }
        float4 vkt = ((const float4*)g_kti)[b * 256 + tid];
        kt2[lL][(j >> 1) + 0] = make_float2(vkt.x, vkt.y);
        kt2[lL][(j >> 1) + 1] = make_float2(vkt.z, vkt.w);
    }
    float s1[NPOS];
    #pragma unroll
    for (int p = 0; p < NPOS; p++)
        s1[p] = __half2float(g_s1h[(r0 + p) * 256 + tid]);
    __syncthreads();

    const int q = tid >> 4;
    const int l = tid & 15;

    const __half2* xp[NPOS];
    #pragma unroll
    for (int p = 0; p < NPOS; p++)
        xp[p] = (const __half2*)xs_h[p] + q * 32;

    float s2[NPOS];
    #pragma unroll
    for (int p = 0; p < NPOS; p++) s2[p] = 0.f;
    #pragma unroll
    for (int j2 = 0; j2 < 32; j2++) {
        const float2 kt = kt2[l][j2];
        #pragma unroll
        for (int p = 0; p < NPOS; p++) {
            const float2 xv = __half22float2(xp[p][j2]);
            s2[p] += xv.x * kt.x + xv.y * kt.y;
        }
    }

    float m1[NPOS], m2[NPOS];
    #pragma unroll
    for (int p = 0; p < NPOS; p++) { m1[p] = s1[p]; m2[p] = s2[p]; }
    #pragma unroll
    for (int o = 8; o > 0; o >>= 1) {
        #pragma unroll
        for (int p = 0; p < NPOS; p++) {
            m1[p] = fmaxf(m1[p], __shfl_xor_sync(0xffffffffu, m1[p], o));
            m2[p] = fmaxf(m2[p], __shfl_xor_sync(0xffffffffu, m2[p], o));
        }
    }
    float e1[NPOS], e2[NPOS], z1[NPOS], z2[NPOS];
    #pragma unroll
    for (int p = 0; p < NPOS; p++) {
        e1[p] = expf(s1[p] - m1[p]); e2[p] = expf(s2[p] - m2[p]);
        z1[p] = e1[p]; z2[p] = e2[p];
    }
    #pragma unroll
    for (int o = 8; o > 0; o >>= 1) {
        #pragma unroll
        for (int p = 0; p < NPOS; p++) {
            z1[p] += __shfl_xor_sync(0xffffffffu, z1[p], o);
            z2[p] += __shfl_xor_sync(0xffffffffu, z2[p], o);
        }
    }
    #pragma unroll
    for (int p = 0; p < NPOS; p++) {
        att1[p][q][l] = e1[p] / z1[p];
        g_att2[(r0 + p) * 256 + tid] = __float2half_rn(e2[p] / z2[p]);
    }
    __syncthreads();

    const int qq = tid >> 4;
    const int dv = tid & 15;
    half4* cat4 = (half4*)g_cat;
    #pragma unroll
    for (int p = 0; p < NPOS; p++) {
        float4 o1 = make_float4(0.f, 0.f, 0.f, 0.f);
        #pragma unroll
        for (int ll = 0; ll < H_; ll++) {
            const float a1 = att1[p][qq][ll];
            const half4 hv = vs_h[p][ll * 16 + dv];
            const float2 v0 = __half22float2(hv.a);
            const float2 v1 = __half22float2(hv.b);
            o1.x += a1 * v0.x; o1.y += a1 * v0.y; o1.z += a1 * v1.x; o1.w += a1 * v1.y;
        }
        half4 h;
        h.a = __floats2half2_rn(o1.x, o1.y);
        h.b = __floats2half2_rn(o1.z, o1.w);
        cat4[(r0 + p) * 256 + tid] = h;
    }
}

// ---------------------------------------------------------------------------
extern "C" void kernel_launch(void* const* d_in, const int* in_sizes, int n_in,
                              void* d_out, int out_size)
{
    const float* img   = (const float*)d_in[0];
    const float* text  = (const float*)d_in[1];
    const float* W_kit = (const float*)d_in[2];
    const float* b_kit = (const float*)d_in[3];
    const float* W_vit = (const float*)d_in[4];
    const float* b_vit = (const float*)d_in[5];
    const float* W_kti = (const float*)d_in[6];
    const float* b_kti = (const float*)d_in[7];
    const float* W_vti = (const float*)d_in[8];
    const float* b_vti = (const float*)d_in[9];
    const float* W_out = (const float*)d_in[10];
    const float* b_out = (const float*)d_in[11];
    float* out = (float*)d_out;

    __half *a16, *vit, *cat, *s1h, *att2, *Qt, *Pt, *wvT, *woT;
    float *cvec;
    cudaGetSymbolAddress((void**)&a16, g_a16);
    cudaGetSymbolAddress((void**)&vit, g_vit);
    cudaGetSymbolAddress((void**)&cat, g_cat);
    cudaGetSymbolAddress((void**)&s1h, g_s1h);
    cudaGetSymbolAddress((void**)&att2, g_att2);
    cudaGetSymbolAddress((void**)&Qt, g_Qt);
    cudaGetSymbolAddress((void**)&Pt, g_Pt);
    cudaGetSymbolAddress((void**)&wvT, g_wvT);
    cudaGetSymbolAddress((void**)&woT, g_woT);
    cudaGetSymbolAddress((void**)&cvec, g_c);

    static cudaStream_t sA = nullptr, sB = nullptr;
    static cudaEvent_t evRoot = nullptr, evA = nullptr, evB = nullptr;
    if (!sA) {
        cudaStreamCreateWithFlags(&sA, cudaStreamNonBlocking);
        cudaStreamCreateWithFlags(&sB, cudaStreamNonBlocking);
        cudaEventCreateWithFlags(&evRoot, cudaEventDisableTiming);
        cudaEventCreateWithFlags(&evA, cudaEventDisableTiming);
        cudaEventCreateWithFlags(&evB, cudaEventDisableTiming);
        cudaFuncSetAttribute(gemm_tc, cudaFuncAttributeMaxDynamicSharedMemorySize, GEMM_SMEM);
    }

    // fork side streams off the capture-origin stream
    cudaEventRecord(evRoot, 0);
    cudaStreamWaitEvent(sA, evRoot, 0);
    cudaStreamWaitEvent(sB, evRoot, 0);

    // stream A: text-side prep (off critical path until attention)
    small_proj<<<dim3(E_ / 256, B_), 256, 0, sA>>>(text, W_kti, b_kti, W_vti, b_vti);
    compute_Pt<<<dim3(4, 256), 256, 0, sA>>>(W_out);
    cudaEventRecord(evA, sA);

    // stream B: img conversion (parallel with main prep)
    cvt_img<<<(M1 * E_ / 4) / 256, 256, 0, sB>>>(img, a16);
    cudaEventRecord(evB, sB);

    // main: weight transposes -> Qt, c
    transpose_all<<<dim3(32, 32, 3), dim3(32, 8)>>>(W_kit, W_vit, W_out);
    compute_Q<<<dim3(4, 256), 256>>>(text);
    compute_c<<<B_, 256>>>(text, b_kit);

    // GEMM1 (whole): v_it projection + img-attn logits (c folded via bias)
    cudaStreamWaitEvent(0, evB, 0);
    gemm_tc<<<dim3(10, 256), 128, GEMM_SMEM>>>(
        a16, 1024, wvT, b_vit, 0, vit, 1024, 0, 0, 1,
        a16, 1024, Qt, cvec, 256, s1h, 256, 256 * E_, 0, 1,
        8, 32, 4096, 0);

    // fused attention -> img_out (fp16) + att2 weights (fp16)
    cudaStreamWaitEvent(0, evA, 0);
    attention_pos<<<dim3(S_ / NPOS, B_), 256>>>();

    // single fused final projection (linearMap=1: cheap K=256 tiles in tail)
    gemm_tc<<<dim3(16, 256), 128, GEMM_SMEM>>>(
        cat, 1024, woT, b_out, 0, out, 1024, 0, 0, 0,
        att2, 256, Pt, b_out, 0, out, 1024, 256 * E_, 4096, 0,
        8, 32, 8192, 1);
}